// round 3
// baseline (speedup 1.0000x reference)
#include <cuda_runtime.h>

// Shape (B=2, C=1, D=160, H=192, W=224), win=5, eps=1e-8
#define DD 160
#define HH 192
#define WW 224
#define BB 2
#define HW (HH * WW)
#define TX 32
#define TY 8
#define CHUNK 40                  // z-outputs per block; 160/40 = 4 chunks
#define GX (WW / TX)              // 7
#define GY (HH / TY)              // 24
#define NCZ (DD / CHUNK)          // 4
#define GZ (BB * NCZ)             // 8
#define NBLOCKS (GX * GY * GZ)    // 1344
#define NTOT ((double)BB * DD * HH * WW)

__device__ double g_partials[NBLOCKS];
__device__ unsigned int g_count = 0;

// x-box sum of (I, J, I2, J2, IJ) for one (row, x) entry, from float2 smem.
#define XSUM_ONE(YY, X) do {                                                      \
    float2 v0 = sIJ[YY][(X)    ];                                                 \
    float2 v1 = sIJ[YY][(X) + 1];                                                 \
    float2 v2 = sIJ[YY][(X) + 2];                                                 \
    float2 v3 = sIJ[YY][(X) + 3];                                                 \
    float2 v4 = sIJ[YY][(X) + 4];                                                 \
    float a0 = v0.x + v1.x + v2.x + v3.x + v4.x;                                  \
    float a1 = v0.y + v1.y + v2.y + v3.y + v4.y;                                  \
    float a2 = fmaf(v4.x, v4.x, fmaf(v3.x, v3.x,                                  \
               fmaf(v2.x, v2.x, fmaf(v1.x, v1.x, v0.x * v0.x))));                 \
    float a3 = fmaf(v4.y, v4.y, fmaf(v3.y, v3.y,                                  \
               fmaf(v2.y, v2.y, fmaf(v1.y, v1.y, v0.y * v0.y))));                 \
    float a4 = fmaf(v4.x, v4.y, fmaf(v3.x, v3.y,                                  \
               fmaf(v2.x, v2.y, fmaf(v1.x, v1.y, v0.x * v0.y))));                 \
    xs4[YY][X] = make_float4(a0, a1, a2, a3);                                     \
    xs1[YY][X] = a4;                                                              \
} while (0)

// One z-slice through the pipeline. SLOT is a compile-time literal 0..4.
#define STEP(SLOT, ZIN, EMIT) do {                                                \
    const bool zin_ = (ZIN);                                                      \
    {   float vi = 0.f, vj = 0.f;                                                 \
        if (zin_ && ok0) { const int g = base + zoff + roff0; vi = gI[g]; vj = gJ[g]; } \
        sIJ[yy0][xx0] = make_float2(vi, vj);                                      \
        if (has1) {                                                               \
            float wi = 0.f, wj = 0.f;                                             \
            if (zin_ && ok1) { const int g = base + zoff + roff1; wi = gI[g]; wj = gJ[g]; } \
            sIJ[yy1][xx1] = make_float2(wi, wj);                                  \
        }                                                                         \
    }                                                                             \
    __syncthreads();                                                              \
    XSUM_ONE(yyA, xA);                                                            \
    if (hasB) XSUM_ONE(yyB, xB);                                                  \
    __syncthreads();                                                              \
    {   float4 b0 = xs4[ly    ][lx];                                              \
        float4 b1 = xs4[ly + 1][lx];                                              \
        float4 b2 = xs4[ly + 2][lx];                                              \
        float4 b3 = xs4[ly + 3][lx];                                              \
        float4 b4 = xs4[ly + 4][lx];                                              \
        float c0 = xs1[ly    ][lx];                                               \
        float c1 = xs1[ly + 1][lx];                                               \
        float c2 = xs1[ly + 2][lx];                                               \
        float c3 = xs1[ly + 3][lx];                                               \
        float c4 = xs1[ly + 4][lx];                                               \
        const float q0 = b0.x + b1.x + b2.x + b3.x + b4.x;                        \
        const float q1 = b0.y + b1.y + b2.y + b3.y + b4.y;                        \
        const float q2 = b0.z + b1.z + b2.z + b3.z + b4.z;                        \
        const float q3 = b0.w + b1.w + b2.w + b3.w + b4.w;                        \
        const float q4 = c0 + c1 + c2 + c3 + c4;                                  \
        SI  += q0 - rI [SLOT]; rI [SLOT] = q0;                                    \
        SJ  += q1 - rJ [SLOT]; rJ [SLOT] = q1;                                    \
        SII += q2 - rII[SLOT]; rII[SLOT] = q2;                                    \
        SJJ += q3 - rJJ[SLOT]; rJJ[SLOT] = q3;                                    \
        SIJ += q4 - rIJ[SLOT]; rIJ[SLOT] = q4;                                    \
    }                                                                             \
    if (EMIT) {                                                                   \
        const float inv = 1.0f / 125.0f, wsz = 125.0f;                            \
        const float uI = SI * inv, uJ = SJ * inv;                                 \
        const float cross = SIJ - uJ * SI - uI * SJ + uI * uJ * wsz;              \
        const float Iv = SII - 2.0f * uI * SI + uI * uI * wsz;                    \
        const float Jv = SJJ - 2.0f * uJ * SJ + uJ * uJ * wsz;                    \
        const float cc = (cross * cross) / (Iv * Jv + 1e-8f);                     \
        acc = fmaf(cc, gW[woff], acc);                                            \
        woff += HW;                                                               \
    }                                                                             \
    zoff += HW; zl += 1;                                                          \
} while (0)

__global__ __launch_bounds__(256)
void ncc_fused(const float* __restrict__ gI,
               const float* __restrict__ gJ,
               const float* __restrict__ gW,
               float* __restrict__ out)
{
    __shared__ float2 sIJ[TY + 4][TX + 4];   // raw I,J slice tile with halo
    __shared__ float4 xs4[TY + 4][TX];       // x-box sums of (I, J, I2, J2)
    __shared__ float  xs1[TY + 4][TX];       // x-box sum of IJ
    __shared__ double sred[256];
    __shared__ int s_last;

    const int tid = threadIdx.x;
    const int x0 = blockIdx.x * TX;
    const int y0 = blockIdx.y * TY;
    const int cz = blockIdx.z % NCZ;
    const int b  = blockIdx.z / NCZ;
    const int z0 = cz * CHUNK;
    const int lx = tid & 31;
    const int ly = tid >> 5;
    const int base = b * (DD * HW);          // < 2^24 elements, int is safe

    // ---- hoisted load-stage mapping (2 entries/thread over 12x36 halo tile) ----
    const int i0  = tid;
    const int yy0 = i0 / (TX + 4), xx0 = i0 - yy0 * (TX + 4);
    const int gy0 = y0 + yy0 - 2,  gx0 = x0 + xx0 - 2;
    const bool ok0 = ((unsigned)gy0 < HH) && ((unsigned)gx0 < WW);
    const int roff0 = ok0 ? gy0 * WW + gx0 : 0;

    const int i1  = tid + 256;
    const bool has1 = (i1 < (TY + 4) * (TX + 4));   // 432 entries
    int yy1 = 0, xx1 = 0, roff1 = 0; bool ok1 = false;
    if (has1) {
        yy1 = i1 / (TX + 4); xx1 = i1 - yy1 * (TX + 4);
        const int gy1 = y0 + yy1 - 2, gx1 = x0 + xx1 - 2;
        ok1 = ((unsigned)gy1 < HH) && ((unsigned)gx1 < WW);
        roff1 = ok1 ? gy1 * WW + gx1 : 0;
    }

    // ---- hoisted x-sum mapping (384 entries) ----
    const int yyA = tid >> 5, xA = tid & 31;
    const bool hasB = (tid < (TY + 4) * TX - 256);   // 128 extra entries
    const int eB = tid + 256;
    const int yyB = eB >> 5, xB = eB & 31;

    // ---- z ring (statically indexed) + running window sums ----
    float rI[5]  = {0, 0, 0, 0, 0}, rJ[5]  = {0, 0, 0, 0, 0};
    float rII[5] = {0, 0, 0, 0, 0}, rJJ[5] = {0, 0, 0, 0, 0};
    float rIJ[5] = {0, 0, 0, 0, 0};
    float SI = 0.f, SJ = 0.f, SII = 0.f, SJJ = 0.f, SIJ = 0.f;
    float acc = 0.f;

    int zl   = z0 - 2;
    int zoff = zl * HW;
    int woff = base + z0 * HW + (y0 + ly) * WW + (x0 + lx);

    // ---- prime: slices z0-2 .. z0+1 into slots 0..3 ----
    STEP(0, zl >= 0, false);
    STEP(1, zl >= 0, false);
    STEP(2, zl >= 0, false);
    STEP(3, zl >= 0, false);

    // ---- main: 40 slices, slots cycle 4,0,1,2,3 ----
#pragma unroll 1
    for (int grp = 0; grp < CHUNK / 5; ++grp) {
        STEP(4, zl < DD, true);
        STEP(0, zl < DD, true);
        STEP(1, zl < DD, true);
        STEP(2, zl < DD, true);
        STEP(3, zl < DD, true);
    }

    // ---- block reduction (deterministic) ----
    sred[tid] = (double)acc;
    __syncthreads();
    for (int s = 128; s > 0; s >>= 1) {
        if (tid < s) sred[tid] += sred[tid + s];
        __syncthreads();
    }
    if (tid == 0) {
        const int bidx = ((int)blockIdx.z * GY + (int)blockIdx.y) * GX + (int)blockIdx.x;
        g_partials[bidx] = sred[0];
        __threadfence();
        const unsigned v = atomicAdd(&g_count, 1u);
        s_last = (v == NBLOCKS - 1);
    }
    __syncthreads();

    // ---- last block folds all partials in fixed order ----
    if (s_last) {
        double s = 0.0;
        for (int i = tid; i < NBLOCKS; i += 256) s += g_partials[i];
        sred[tid] = s;
        __syncthreads();
        for (int k = 128; k > 0; k >>= 1) {
            if (tid < k) sred[tid] += sred[tid + k];
            __syncthreads();
        }
        if (tid == 0) {
            out[0] = (float)(-sred[0] / NTOT);
            g_count = 0;   // reset for next graph replay
        }
    }
}

extern "C" void kernel_launch(void* const* d_in, const int* in_sizes, int n_in,
                              void* d_out, int out_size)
{
    const float* I  = (const float*)d_in[0];
    const float* J  = (const float*)d_in[1];
    const float* Wt = (const float*)d_in[2];
    float* out = (float*)d_out;

    dim3 grid(GX, GY, GZ);
    ncc_fused<<<grid, 256>>>(I, J, Wt, out);
}

// round 5
// speedup vs baseline: 1.2535x; 1.2535x over previous
#include <cuda_runtime.h>

// Shape (B=2, C=1, D=160, H=192, W=224), win=5, eps=1e-8
#define DD 160
#define HH 192
#define WW 224
#define BB 2
#define HW (HH * WW)
#define TX 32
#define TY 12
#define RR 16                    // y rows per block = TY + 4
#define RCOLS 36                 // raw cols = TX + 4
#define CHUNK 40                 // z-outputs per block
#define GX (WW / TX)             // 7
#define GY (HH / TY)             // 16
#define NCZ (DD / CHUNK)         // 4
#define GZ (BB * NCZ)            // 8
#define NBLOCKS (GX * GY * GZ)   // 896
#define NT 512
#define NTOT ((double)BB * DD * HH * WW)

__device__ double g_partials[NBLOCKS];
__device__ unsigned int g_count = 0;

__device__ __forceinline__ float ncc_cc(float4 s, float sij)
{
    const float wsz = 125.0f, inv = 1.0f / 125.0f;
    const float uI = s.x * inv, uJ = s.y * inv;
    const float cross = sij - uJ * s.x - uI * s.y + uI * uJ * wsz;
    const float Iv = s.z - 2.0f * uI * s.x + uI * uI * wsz;
    const float Jv = s.w - 2.0f * uJ * s.y + uJ * uJ * wsz;
    return (cross * cross) / (Iv * Jv + 1e-8f);
}

// y-box + emit for 2 outputs (rows yb, yb+1) from zs buffer PB. tid<192 only.
#define YEMIT(PB) do {                                                          \
    if (tid < 192) {                                                            \
        float4 sA = make_float4(0.f,0.f,0.f,0.f);                               \
        float4 sB = make_float4(0.f,0.f,0.f,0.f);                               \
        float sA1 = 0.f, sB1 = 0.f;                                             \
        _Pragma("unroll")                                                       \
        for (int j = 0; j < 6; ++j) {                                           \
            float4 v = zs4[PB][yb + j][xx2];                                    \
            float  u = zs1[PB][yb + j][xx2];                                    \
            if (j < 5) { sA.x += v.x; sA.y += v.y; sA.z += v.z; sA.w += v.w;    \
                         sA1 += u; }                                            \
            if (j > 0) { sB.x += v.x; sB.y += v.y; sB.z += v.z; sB.w += v.w;    \
                         sB1 += u; }                                            \
        }                                                                       \
        acc = fmaf(ncc_cc(sA, sA1), w0, acc);                                   \
        acc = fmaf(ncc_cc(sB, sB1), w1, acc);                                   \
        woff += HW;                                                             \
    }                                                                           \
} while (0)

// One z-slice. SLOT/CB/DOY/DOPRE are compile-time literals.
// CB = it&1 (xsum reads sraw[CB], writes zs[CB]); YEMIT reads zs[CB^1].
#define STEP(SLOT, CB, DOY, DOPRE) do {                                         \
    float vi0 = 0.f, vj0 = 0.f, vi1 = 0.f, vj1 = 0.f;                           \
    if (DOPRE) {                                                                \
        const bool nz = ((unsigned)zl_next < (unsigned)DD);                     \
        if (nz && ok0) { const int g = pB0 + nzoff; vi0 = gI[g]; vj0 = gJ[g]; } \
        if (has1 && nz && ok1) { const int g = pB1 + nzoff;                     \
                                 vi1 = gI[g]; vj1 = gJ[g]; }                    \
    }                                                                           \
    if (DOY) { if (tid < 192) { w0 = gW[woff]; w1 = gW[woff + WW]; } }          \
    __syncthreads();                                                            \
    if (DOY) YEMIT((CB) ^ 1);                                                   \
    {                                                                           \
        float2 v0 = sraw[CB][xr][xx + 0];                                       \
        float2 v1 = sraw[CB][xr][xx + 1];                                       \
        float2 v2 = sraw[CB][xr][xx + 2];                                       \
        float2 v3 = sraw[CB][xr][xx + 3];                                       \
        float2 v4 = sraw[CB][xr][xx + 4];                                       \
        const float a0 = v0.x + v1.x + v2.x + v3.x + v4.x;                      \
        const float a1 = v0.y + v1.y + v2.y + v3.y + v4.y;                      \
        const float a2 = fmaf(v4.x, v4.x, fmaf(v3.x, v3.x,                      \
                         fmaf(v2.x, v2.x, fmaf(v1.x, v1.x, v0.x * v0.x))));     \
        const float a3 = fmaf(v4.y, v4.y, fmaf(v3.y, v3.y,                      \
                         fmaf(v2.y, v2.y, fmaf(v1.y, v1.y, v0.y * v0.y))));     \
        const float a4 = fmaf(v4.x, v4.y, fmaf(v3.x, v3.y,                      \
                         fmaf(v2.x, v2.y, fmaf(v1.x, v1.y, v0.x * v0.y))));     \
        SI  += a0 - r0[SLOT]; r0[SLOT] = a0;                                    \
        SJ  += a1 - r1[SLOT]; r1[SLOT] = a1;                                    \
        SII += a2 - r2[SLOT]; r2[SLOT] = a2;                                    \
        SJJ += a3 - r3[SLOT]; r3[SLOT] = a3;                                    \
        SIJ += a4 - r4[SLOT]; r4[SLOT] = a4;                                    \
        zs4[CB][xr][xx] = make_float4(SI, SJ, SII, SJJ);                        \
        zs1[CB][xr][xx] = SIJ;                                                  \
    }                                                                           \
    if (DOPRE) {                                                                \
        sraw[(CB) ^ 1][row0][col0] = make_float2(vi0, vj0);                     \
        if (has1) sraw[(CB) ^ 1][row1][col1] = make_float2(vi1, vj1);           \
    }                                                                           \
    zl_next += 1; nzoff += HW;                                                  \
} while (0)

__global__ __launch_bounds__(NT, 2)
void ncc_fused(const float* __restrict__ gI,
               const float* __restrict__ gJ,
               const float* __restrict__ gW,
               float* __restrict__ out)
{
    __shared__ float2 sraw[2][RR][RCOLS];   // raw (I,J) slice, double-buffered
    __shared__ float4 zs4[2][RR][TX];       // xz-box sums of (I, J, I2, J2)
    __shared__ float  zs1[2][RR][TX];       // xz-box sum of IJ
    __shared__ double sred[NT];
    __shared__ int s_last;

    const int tid = threadIdx.x;
    const int x0 = blockIdx.x * TX;
    const int y0 = blockIdx.y * TY;
    const int cz = blockIdx.z % NCZ;
    const int b  = blockIdx.z / NCZ;
    const int z0 = cz * CHUNK;
    const int base = b * (DD * HW);

    // ---- raw load mapping: 576 float2 entries over 512 threads ----
    const int row0 = tid / RCOLS, col0 = tid - row0 * RCOLS;
    const int gy0 = y0 + row0 - 2, gx0 = x0 + col0 - 2;
    const bool ok0 = ((unsigned)gy0 < HH) && ((unsigned)gx0 < WW);
    const int pB0 = base + (ok0 ? gy0 * WW + gx0 : 0);

    const bool has1 = (tid < RR * RCOLS - NT);   // 64 extra entries
    const int e1 = tid + NT;
    const int row1 = e1 / RCOLS, col1 = e1 - row1 * RCOLS;
    const int gy1 = y0 + row1 - 2, gx1 = x0 + col1 - 2;
    const bool ok1 = ((unsigned)gy1 < HH) && ((unsigned)gx1 < WW);
    const int pB1 = base + (ok1 ? gy1 * WW + gx1 : 0);

    // ---- xsum entry mapping: one (row, x) per thread ----
    const int xr = tid >> 5;        // 0..15
    const int xx = tid & 31;        // 0..31

    // ---- y-stage mapping (tid < 192): 2 y-outputs per thread ----
    const int xx2 = tid & 31;
    const int yb  = (tid >> 5) * 2;  // 0,2,4,6,8,10
    int woff = base + z0 * HW + (y0 + yb) * WW + (x0 + xx2);
    float w0 = 0.f, w1 = 0.f;

    // ---- per-entry z ring (static-indexed) + running sums ----
    float r0[5] = {0,0,0,0,0}, r1[5] = {0,0,0,0,0}, r2[5] = {0,0,0,0,0};
    float r3[5] = {0,0,0,0,0}, r4[5] = {0,0,0,0,0};
    float SI = 0.f, SJ = 0.f, SII = 0.f, SJJ = 0.f, SIJ = 0.f;
    float acc = 0.f;

    // ---- prologue: load slice z0-2 into sraw[0] ----
    {
        const int zp = z0 - 2;
        const bool nz = (zp >= 0);
        const int zo = zp * HW;
        float vi0 = 0.f, vj0 = 0.f, vi1 = 0.f, vj1 = 0.f;
        if (nz && ok0) { const int g = pB0 + zo; vi0 = gI[g]; vj0 = gJ[g]; }
        if (has1 && nz && ok1) { const int g = pB1 + zo; vi1 = gI[g]; vj1 = gJ[g]; }
        sraw[0][row0][col0] = make_float2(vi0, vj0);
        if (has1) sraw[0][row1][col1] = make_float2(vi1, vj1);
    }

    int zl_next = z0 - 1;            // slice prefetched by step it is it+1 -> z0-2+it+1
    int nzoff = zl_next * HW;

    // its 0..8
    STEP(0, 0, false, true);
    STEP(1, 1, false, true);
    STEP(2, 0, false, true);
    STEP(3, 1, false, true);
    STEP(4, 0, false, true);
    STEP(0, 1, true,  true);
    STEP(1, 0, true,  true);
    STEP(2, 1, true,  true);
    STEP(3, 0, true,  true);

    // its 9..38 : 3 x 10 steps (parity-periodic)
#pragma unroll 1
    for (int g = 0; g < 3; ++g) {
        STEP(4, 1, true, true);
        STEP(0, 0, true, true);
        STEP(1, 1, true, true);
        STEP(2, 0, true, true);
        STEP(3, 1, true, true);
        STEP(4, 0, true, true);
        STEP(0, 1, true, true);
        STEP(1, 0, true, true);
        STEP(2, 1, true, true);
        STEP(3, 0, true, true);
    }

    // its 39..43
    STEP(4, 1, true, true);
    STEP(0, 0, true, true);
    STEP(1, 1, true, true);
    STEP(2, 0, true, true);
    STEP(3, 1, true, false);         // it=43: no prefetch

    // ---- epilogue: emit z0+39 from zs[1] ----
    if (tid < 192) { w0 = gW[woff]; w1 = gW[woff + WW]; }
    __syncthreads();
    YEMIT(1);

    // ---- block reduction (deterministic) ----
    sred[tid] = (double)acc;
    __syncthreads();
    for (int s = NT / 2; s > 0; s >>= 1) {
        if (tid < s) sred[tid] += sred[tid + s];
        __syncthreads();
    }
    if (tid == 0) {
        const int bidx = ((int)blockIdx.z * GY + (int)blockIdx.y) * GX + (int)blockIdx.x;
        g_partials[bidx] = sred[0];
        __threadfence();
        const unsigned v = atomicAdd(&g_count, 1u);
        s_last = (v == NBLOCKS - 1);
    }
    __syncthreads();

    // ---- last block folds all partials in fixed order ----
    if (s_last) {
        double s = 0.0;
        for (int i = tid; i < NBLOCKS; i += NT) s += g_partials[i];
        sred[tid] = s;
        __syncthreads();
        for (int k = NT / 2; k > 0; k >>= 1) {
            if (tid < k) sred[tid] += sred[tid + k];
            __syncthreads();
        }
        if (tid == 0) {
            out[0] = (float)(-sred[0] / NTOT);
            g_count = 0;   // reset for next graph replay
        }
    }
}

extern "C" void kernel_launch(void* const* d_in, const int* in_sizes, int n_in,
                              void* d_out, int out_size)
{
    const float* I  = (const float*)d_in[0];
    const float* J  = (const float*)d_in[1];
    const float* Wt = (const float*)d_in[2];
    float* out = (float*)d_out;

    dim3 grid(GX, GY, GZ);
    ncc_fused<<<grid, NT>>>(I, J, Wt, out);
}

// round 6
// speedup vs baseline: 1.4214x; 1.1339x over previous
#include <cuda_runtime.h>

// Shape (B=2, C=1, D=160, H=192, W=224), win=5, eps=1e-8
#define DD 160
#define HH 192
#define WW 224
#define BB 2
#define HW (HH * WW)
#define TX 32
#define TY 12
#define RR 16                    // rows per block = TY + 4
#define RCOLS 36                 // raw cols = TX + 4
#define CHUNK 40                 // z-outputs per block
#define GX (WW / TX)             // 7
#define GY (HH / TY)             // 16
#define NCZ (DD / CHUNK)         // 4
#define GZ (BB * NCZ)            // 8
#define NBLOCKS (GX * GY * GZ)   // 896
#define NT 512
#define NTOT ((double)BB * DD * HH * WW)

// dynamic smem layout (bytes)
#define OFF_RAW   0                            // float2 [2][2][RR][RCOLS] = 18432
#define OFF_ZS4   18432                        // float4 [2][2][RR][TX]   = 32768
#define OFF_ZS1   (18432 + 32768)              // float  [2][2][RR][TX]   = 8192
#define OFF_SRED  (18432 + 32768 + 8192)       // double [16]             = 128
#define OFF_LAST  (OFF_SRED + 128)             // int
#define SMEM_BYTES (OFF_LAST + 16)

__device__ double g_partials[NBLOCKS];
__device__ unsigned int g_count = 0;

__device__ __forceinline__ float ncc_cc(float4 s, float sij)
{
    const float wsz = 125.0f, inv = 1.0f / 125.0f;
    const float uI = s.x * inv, uJ = s.y * inv;
    const float cross = sij - uJ * s.x - uI * s.y + uI * uJ * wsz;
    const float Iv = s.z - 2.0f * uI * s.x + uI * uI * wsz;
    const float Jv = s.w - 2.0f * uJ * s.y + uJ * uJ * wsz;
    return (cross * cross) / (Iv * Jv + 1e-8f);
}

// x-box sums + z-ring update for one slice S (0/1) of current pair bi.
#define XR(SLOT, S) do {                                                        \
    float2 v0 = sraw[bi][S][xr][xx + 0];                                        \
    float2 v1 = sraw[bi][S][xr][xx + 1];                                        \
    float2 v2 = sraw[bi][S][xr][xx + 2];                                        \
    float2 v3 = sraw[bi][S][xr][xx + 3];                                        \
    float2 v4 = sraw[bi][S][xr][xx + 4];                                        \
    const float a0 = v0.x + v1.x + v2.x + v3.x + v4.x;                          \
    const float a1 = v0.y + v1.y + v2.y + v3.y + v4.y;                          \
    const float a2 = fmaf(v4.x, v4.x, fmaf(v3.x, v3.x,                          \
                     fmaf(v2.x, v2.x, fmaf(v1.x, v1.x, v0.x * v0.x))));         \
    const float a3 = fmaf(v4.y, v4.y, fmaf(v3.y, v3.y,                          \
                     fmaf(v2.y, v2.y, fmaf(v1.y, v1.y, v0.y * v0.y))));         \
    const float a4 = fmaf(v4.x, v4.y, fmaf(v3.x, v3.y,                          \
                     fmaf(v2.x, v2.y, fmaf(v1.x, v1.y, v0.x * v0.y))));         \
    SI  += a0 - r0[SLOT]; r0[SLOT] = a0;                                        \
    SJ  += a1 - r1[SLOT]; r1[SLOT] = a1;                                        \
    SII += a2 - r2[SLOT]; r2[SLOT] = a2;                                        \
    SJJ += a3 - r3[SLOT]; r3[SLOT] = a3;                                        \
    SIJ += a4 - r4[SLOT]; r4[SLOT] = a4;                                        \
    zs4[bi][S][xr][xx] = make_float4(SI, SJ, SII, SJJ);                         \
    zs1[bi][S][xr][xx] = SIJ;                                                   \
} while (0)

// One phase = two z-slices, one barrier. SA/SB/DOY compile-time literals.
#define PHASE(SA, SB, DOY) do {                                                 \
    float pAi0 = 0.f, pAj0 = 0.f, pAi1 = 0.f, pAj1 = 0.f;                       \
    float pBi0 = 0.f, pBj0 = 0.f, pBi1 = 0.f, pBj1 = 0.f;                       \
    {                                                                           \
        const bool zA = (zpre < DD);                                            \
        const bool zB = (zpre + 1 < DD);                                        \
        if (zA && ok0) { const int g = pB0 + preoff;      pAi0 = gI[g]; pAj0 = gJ[g]; } \
        if (zB && ok0) { const int g = pB0 + preoff + HW; pBi0 = gI[g]; pBj0 = gJ[g]; } \
        if (has1) {                                                             \
            if (zA && ok1) { const int g = pB1 + preoff;      pAi1 = gI[g]; pAj1 = gJ[g]; } \
            if (zB && ok1) { const int g = pB1 + preoff + HW; pBi1 = gI[g]; pBj1 = gJ[g]; } \
        }                                                                       \
    }                                                                           \
    float w0 = 0.f, w1 = 0.f;                                                   \
    if (DOY && emit_ok) { w0 = gW[woff]; w1 = gW[woff + WW]; }                  \
    XR(SA, 0);                                                                  \
    XR(SB, 1);                                                                  \
    {                                                                           \
        const int nb = bi ^ 1;                                                  \
        sraw[nb][0][row0][col0] = make_float2(pAi0, pAj0);                      \
        sraw[nb][1][row0][col0] = make_float2(pBi0, pBj0);                      \
        if (has1) {                                                             \
            sraw[nb][0][row1][col1] = make_float2(pAi1, pAj1);                  \
            sraw[nb][1][row1][col1] = make_float2(pBi1, pBj1);                  \
        }                                                                       \
    }                                                                           \
    __syncthreads();                                                            \
    if (DOY && emit_ok) {                                                       \
        float4 sA = make_float4(0.f, 0.f, 0.f, 0.f);                            \
        float4 sB = make_float4(0.f, 0.f, 0.f, 0.f);                            \
        float sA1 = 0.f, sB1 = 0.f;                                             \
        _Pragma("unroll")                                                       \
        for (int j = 0; j < 6; ++j) {                                           \
            float4 v = zs4[bi][esl][yb + j][exx];                               \
            float  u = zs1[bi][esl][yb + j][exx];                               \
            if (j < 5) { sA.x += v.x; sA.y += v.y; sA.z += v.z; sA.w += v.w;    \
                         sA1 += u; }                                            \
            if (j > 0) { sB.x += v.x; sB.y += v.y; sB.z += v.z; sB.w += v.w;    \
                         sB1 += u; }                                            \
        }                                                                       \
        acc = fmaf(ncc_cc(sA, sA1), w0, acc);                                   \
        acc = fmaf(ncc_cc(sB, sB1), w1, acc);                                   \
        woff += 2 * HW;                                                         \
    }                                                                           \
    zpre += 2; preoff += 2 * HW; bi ^= 1;                                       \
} while (0)

__global__ __launch_bounds__(NT, 2)
void ncc_fused(const float* __restrict__ gI,
               const float* __restrict__ gJ,
               const float* __restrict__ gW,
               float* __restrict__ out)
{
    extern __shared__ unsigned char dsm[];
    float2 (*sraw)[2][RR][RCOLS] = (float2 (*)[2][RR][RCOLS])(dsm + OFF_RAW);
    float4 (*zs4)[2][RR][TX]     = (float4 (*)[2][RR][TX])(dsm + OFF_ZS4);
    float  (*zs1)[2][RR][TX]     = (float  (*)[2][RR][TX])(dsm + OFF_ZS1);
    double* sred  = (double*)(dsm + OFF_SRED);
    int*    slast = (int*)(dsm + OFF_LAST);

    const int tid = threadIdx.x;
    const int lane = tid & 31;
    const int warp = tid >> 5;
    const int x0 = blockIdx.x * TX;
    const int y0 = blockIdx.y * TY;
    const int cz = blockIdx.z % NCZ;
    const int b  = blockIdx.z / NCZ;
    const int z0 = cz * CHUNK;
    const int base = b * (DD * HW);

    // ---- raw load mapping: 576 float2 entries over 512 threads ----
    const int row0 = tid / RCOLS, col0 = tid - row0 * RCOLS;
    const int gy0 = y0 + row0 - 2, gx0 = x0 + col0 - 2;
    const bool ok0 = ((unsigned)gy0 < HH) && ((unsigned)gx0 < WW);
    const int pB0 = base + (ok0 ? gy0 * WW + gx0 : 0);

    const bool has1 = (tid < RR * RCOLS - NT);   // 64 extra entries
    const int e1 = tid + NT;
    const int row1 = e1 / RCOLS, col1 = e1 - row1 * RCOLS;
    const int gy1 = y0 + row1 - 2, gx1 = x0 + col1 - 2;
    const bool ok1 = ((unsigned)gy1 < HH) && ((unsigned)gx1 < WW);
    const int pB1 = base + (ok1 ? gy1 * WW + gx1 : 0);

    // ---- xsum entry: one (row, x) per thread ----
    const int xr = warp;            // 0..15
    const int xx = lane;            // 0..31

    // ---- y-emit mapping: 384 threads, 2 slices x 192 ----
    const bool emit_ok = (tid < 384);
    const int esl = tid / 192;                 // which slice of the pair
    const int eu  = tid - esl * 192;
    const int exx = eu & 31;
    const int yb  = (eu >> 5) * 2;             // 0,2,..,10
    int woff = base + (z0 + esl) * HW + (y0 + yb) * WW + (x0 + exx);

    // ---- z ring (static slots) + running sums ----
    float r0[5] = {0,0,0,0,0}, r1[5] = {0,0,0,0,0}, r2[5] = {0,0,0,0,0};
    float r3[5] = {0,0,0,0,0}, r4[5] = {0,0,0,0,0};
    float SI = 0.f, SJ = 0.f, SII = 0.f, SJJ = 0.f, SIJ = 0.f;
    float acc = 0.f;

    // ---- prologue: slices z0-2, z0-1 into pair 0 ----
    {
        const int zp = z0 - 2;
        const int zo = zp * HW;
        float a0i = 0.f, a0j = 0.f, a1i = 0.f, a1j = 0.f;
        float b0i = 0.f, b0j = 0.f, b1i = 0.f, b1j = 0.f;
        if (zp >= 0 && ok0)     { const int g = pB0 + zo;      a0i = gI[g]; a0j = gJ[g]; }
        if (zp + 1 >= 0 && ok0) { const int g = pB0 + zo + HW; b0i = gI[g]; b0j = gJ[g]; }
        if (has1) {
            if (zp >= 0 && ok1)     { const int g = pB1 + zo;      a1i = gI[g]; a1j = gJ[g]; }
            if (zp + 1 >= 0 && ok1) { const int g = pB1 + zo + HW; b1i = gI[g]; b1j = gJ[g]; }
        }
        sraw[0][0][row0][col0] = make_float2(a0i, a0j);
        sraw[0][1][row0][col0] = make_float2(b0i, b0j);
        if (has1) {
            sraw[0][0][row1][col1] = make_float2(a1i, a1j);
            sraw[0][1][row1][col1] = make_float2(b1i, b1j);
        }
        __syncthreads();
    }

    int bi = 0;
    int zpre = z0;               // phase p prefetches slices z0+2p, z0+2p+1
    int preoff = z0 * HW;

    PHASE(0, 1, false);          // p0: slices z0-2, z0-1
    PHASE(2, 3, false);          // p1: slices z0,   z0+1
#pragma unroll 1
    for (int g = 0; g < 4; ++g) {   // p2..p21, 5-phase slot period
        PHASE(4, 0, true);
        PHASE(1, 2, true);
        PHASE(3, 4, true);
        PHASE(0, 1, true);
        PHASE(2, 3, true);
    }

    // ---- reduction: shuffle tree (deterministic) ----
    double a = (double)acc;
#pragma unroll
    for (int off = 16; off > 0; off >>= 1)
        a += __shfl_down_sync(0xffffffffu, a, off);
    if (lane == 0) sred[warp] = a;
    __syncthreads();
    if (warp == 0) {
        double s = (lane < 16) ? sred[lane] : 0.0;
#pragma unroll
        for (int off = 8; off > 0; off >>= 1)
            s += __shfl_down_sync(0xffffffffu, s, off);
        if (lane == 0) {
            const int bidx = ((int)blockIdx.z * GY + (int)blockIdx.y) * GX + (int)blockIdx.x;
            g_partials[bidx] = s;
            __threadfence();
            const unsigned v = atomicAdd(&g_count, 1u);
            *slast = (v == NBLOCKS - 1);
        }
    }
    __syncthreads();

    // ---- last block folds all partials in fixed order ----
    if (*slast) {
        double s = 0.0;
        for (int i = tid; i < NBLOCKS; i += NT) s += g_partials[i];
#pragma unroll
        for (int off = 16; off > 0; off >>= 1)
            s += __shfl_down_sync(0xffffffffu, s, off);
        if (lane == 0) sred[warp] = s;
        __syncthreads();
        if (warp == 0) {
            double t = (lane < 16) ? sred[lane] : 0.0;
#pragma unroll
            for (int off = 8; off > 0; off >>= 1)
                t += __shfl_down_sync(0xffffffffu, t, off);
            if (lane == 0) {
                out[0] = (float)(-t / NTOT);
                g_count = 0;   // reset for next graph replay
            }
        }
    }
}

extern "C" void kernel_launch(void* const* d_in, const int* in_sizes, int n_in,
                              void* d_out, int out_size)
{
    const float* I  = (const float*)d_in[0];
    const float* J  = (const float*)d_in[1];
    const float* Wt = (const float*)d_in[2];
    float* out = (float*)d_out;

    cudaFuncSetAttribute(ncc_fused, cudaFuncAttributeMaxDynamicSharedMemorySize,
                         SMEM_BYTES);
    dim3 grid(GX, GY, GZ);
    ncc_fused<<<grid, NT, SMEM_BYTES>>>(I, J, Wt, out);
}